// round 1
// baseline (speedup 1.0000x reference)
#include <cuda_runtime.h>
#include <math.h>
#include <stdint.h>

// ---------------- problem constants ----------------
#define BATCH 32
#define NNODE 1024
#define NT    32768          // BATCH*NNODE
#define DEG   8
#define NE    262144         // NT*DEG
#define F_IN  64
#define HIDC  128
#define EDIM  16
#define NR    16
#define HD    4
#define HDH   512            // HD*HIDC
#define KEEP1 820
#define KEEP2 656
#define NEG_SLOPE 0.2f

// ---------------- device scratch (no allocations allowed) ----------------
__device__ float g_xl[(size_t)NT * HDH];
__device__ float g_xr[(size_t)NT * HDH];
__device__ float g_h1[(size_t)NT * HIDC];
__device__ float g_hp1[(size_t)NT * HIDC];
__device__ float g_h2[(size_t)NT * HIDC];
__device__ float g_score1[NT];
__device__ float g_score2[NT];
__device__ int   g_keep1[NT];
__device__ int   g_keep2[NT];
__device__ int   g_cnt[NT];
__device__ int   g_pos[NT];
__device__ int   g_row[NT + 1];
__device__ int   g_csr[NE];
__device__ float g_gmx[BATCH * HIDC];
__device__ float g_gav[BATCH * HIDC];

// ---------------- CSR build ----------------
__global__ void zero_kernel() {
    int i = blockIdx.x * blockDim.x + threadIdx.x;
    if (i < NT) { g_cnt[i] = 0; g_pos[i] = 0; }
}

__global__ void count_kernel(const int* __restrict__ dst) {
    int e = blockIdx.x * blockDim.x + threadIdx.x;
    if (e < NE) atomicAdd(&g_cnt[dst[e]], 1);
}

__global__ void scan_kernel() {   // 1 block, 1024 threads; NT = 1024*32
    __shared__ int s[1024];
    int t = threadIdx.x;
    int base = t * 32;
    int vals[32];
    int loc = 0;
#pragma unroll
    for (int j = 0; j < 32; j++) { vals[j] = g_cnt[base + j]; loc += vals[j]; }
    s[t] = loc;
    __syncthreads();
    for (int off = 1; off < 1024; off <<= 1) {
        int v = 0;
        if (t >= off) v = s[t - off];
        __syncthreads();
        s[t] += v;
        __syncthreads();
    }
    int run = s[t] - loc;   // exclusive prefix
#pragma unroll
    for (int j = 0; j < 32; j++) { g_row[base + j] = run; run += vals[j]; }
    if (t == 1023) g_row[NT] = run;
}

__global__ void scatter_kernel(const int* __restrict__ dst) {
    int e = blockIdx.x * blockDim.x + threadIdx.x;
    if (e < NE) {
        int d = dst[e];
        int p = atomicAdd(&g_pos[d], 1);
        g_csr[g_row[d] + p] = e;
    }
}

// ---------------- fp32 SGEMM: C[M,Ncol] = A[M,K] @ W[K,Ncol] + bias ----------------
// BM=64, BN=64, BK=16, 256 threads, 4x4 per thread. M%64==0, Ncol%64==0, K%16==0.
__global__ __launch_bounds__(256)
void sgemm_bias(const float* __restrict__ A, const float* __restrict__ W,
                const float* __restrict__ bias, float* __restrict__ C,
                int M, int K, int Ncol) {
    __shared__ float sA[16][64];
    __shared__ float sB[16][64];
    int tid = threadIdx.x;
    int tx = tid & 15, ty = tid >> 4;
    int row0 = blockIdx.y * 64, col0 = blockIdx.x * 64;
    float acc[4][4];
#pragma unroll
    for (int i = 0; i < 4; i++)
#pragma unroll
        for (int j = 0; j < 4; j++) acc[i][j] = 0.f;

    for (int k0 = 0; k0 < K; k0 += 16) {
#pragma unroll
        for (int i = tid; i < 64 * 16; i += 256) {
            int r = i >> 4, kk = i & 15;
            sA[kk][r] = A[(size_t)(row0 + r) * K + k0 + kk];
        }
#pragma unroll
        for (int i = tid; i < 16 * 64; i += 256) {
            int kk = i >> 6, c = i & 63;
            sB[kk][c] = W[(size_t)(k0 + kk) * Ncol + col0 + c];
        }
        __syncthreads();
#pragma unroll
        for (int kk = 0; kk < 16; kk++) {
            float4 av = *(const float4*)&sA[kk][ty * 4];
            float4 bv = *(const float4*)&sB[kk][tx * 4];
            float a[4] = {av.x, av.y, av.z, av.w};
            float b[4] = {bv.x, bv.y, bv.z, bv.w};
#pragma unroll
            for (int i = 0; i < 4; i++)
#pragma unroll
                for (int j = 0; j < 4; j++) acc[i][j] = fmaf(a[i], b[j], acc[i][j]);
        }
        __syncthreads();
    }
    float4 bv = *(const float4*)(bias + col0 + tx * 4);
    float bb[4] = {bv.x, bv.y, bv.z, bv.w};
#pragma unroll
    for (int i = 0; i < 4; i++) {
        float4 o;
        o.x = acc[i][0] + bb[0];
        o.y = acc[i][1] + bb[1];
        o.z = acc[i][2] + bb[2];
        o.w = acc[i][3] + bb[3];
        *(float4*)(C + (size_t)(row0 + ty * 4 + i) * Ncol + col0 + tx * 4) = o;
    }
}

// ---------------- fused GATv2 edge kernel: warp per dst node, online softmax ----------------
__global__ __launch_bounds__(256)
void gat_kernel(const float* __restrict__ xl, const float* __restrict__ xr,
                const float* __restrict__ ea_g, const float* __restrict__ We,
                const float* __restrict__ att, const float* __restrict__ bias,
                const int* __restrict__ src, const int* __restrict__ kp,
                float* __restrict__ out) {
    __shared__ float sWe[16][512];
    __shared__ float sAtt[512];
    for (int i = threadIdx.x; i < 16 * 512; i += blockDim.x)
        sWe[i >> 9][i & 511] = We[i];
    for (int i = threadIdx.x; i < 512; i += blockDim.x) sAtt[i] = att[i];
    __syncthreads();

    int node = blockIdx.x * (blockDim.x >> 5) + (threadIdx.x >> 5);
    int l4 = (threadIdx.x & 31) * 4;

    float4 xrv[HD], attv[HD], acc[HD];
    float mh[HD], dh[HD];
#pragma unroll
    for (int h = 0; h < HD; h++) {
        xrv[h] = *(const float4*)(xr + (size_t)node * HDH + h * HIDC + l4);
        attv[h] = *(const float4*)(&sAtt[h * HIDC + l4]);
        acc[h] = make_float4(0.f, 0.f, 0.f, 0.f);
        mh[h] = -INFINITY;
        dh[h] = 0.f;
    }

    bool ok = (kp == nullptr) || (kp[node] != 0);
    int beg = g_row[node];
    int end = ok ? g_row[node + 1] : beg;

    for (int idx = beg; idx < end; idx++) {
        int e = g_csr[idx];
        int s = src[e];
        if (kp && !kp[s]) continue;

        const float4* eap = (const float4*)(ea_g + (size_t)e * EDIM);
        float4 ea0 = eap[0], ea1 = eap[1], ea2 = eap[2], ea3 = eap[3];
        float ea[16] = {ea0.x, ea0.y, ea0.z, ea0.w, ea1.x, ea1.y, ea1.z, ea1.w,
                        ea2.x, ea2.y, ea2.z, ea2.w, ea3.x, ea3.y, ea3.z, ea3.w};
        float4 xlv[HD];
        float part[HD];
        const float* xls = xl + (size_t)s * HDH;
#pragma unroll
        for (int h = 0; h < HD; h++) {
            float4 v = *(const float4*)(xls + h * HIDC + l4);
            xlv[h] = v;
            float4 ef = make_float4(0.f, 0.f, 0.f, 0.f);
#pragma unroll
            for (int k = 0; k < 16; k++) {
                float4 w = *(const float4*)(&sWe[k][h * HIDC + l4]);
                ef.x = fmaf(ea[k], w.x, ef.x);
                ef.y = fmaf(ea[k], w.y, ef.y);
                ef.z = fmaf(ea[k], w.z, ef.z);
                ef.w = fmaf(ea[k], w.w, ef.w);
            }
            float4 t;
            t.x = v.x + xrv[h].x + ef.x;
            t.y = v.y + xrv[h].y + ef.y;
            t.z = v.z + xrv[h].z + ef.z;
            t.w = v.w + xrv[h].w + ef.w;
            t.x = t.x > 0.f ? t.x : NEG_SLOPE * t.x;
            t.y = t.y > 0.f ? t.y : NEG_SLOPE * t.y;
            t.z = t.z > 0.f ? t.z : NEG_SLOPE * t.z;
            t.w = t.w > 0.f ? t.w : NEG_SLOPE * t.w;
            part[h] = t.x * attv[h].x + t.y * attv[h].y + t.z * attv[h].z + t.w * attv[h].w;
        }
#pragma unroll
        for (int h = 0; h < HD; h++)
#pragma unroll
            for (int off = 16; off; off >>= 1)
                part[h] += __shfl_xor_sync(0xffffffffu, part[h], off);
#pragma unroll
        for (int h = 0; h < HD; h++) {
            float L = part[h];
            float nm = fmaxf(mh[h], L);
            float sc = expf(mh[h] - nm);  // expf(-inf)=0 on first edge
            float w = expf(L - nm);
            dh[h] = dh[h] * sc + w;
            acc[h].x = acc[h].x * sc + w * xlv[h].x;
            acc[h].y = acc[h].y * sc + w * xlv[h].y;
            acc[h].z = acc[h].z * sc + w * xlv[h].z;
            acc[h].w = acc[h].w * sc + w * xlv[h].w;
            mh[h] = nm;
        }
    }

    float r[HD];
#pragma unroll
    for (int h = 0; h < HD; h++) r[h] = 1.f / (dh[h] + 1e-16f);  // acc==0 when dh==0
    float4 o;
    o.x = 0.25f * (acc[0].x * r[0] + acc[1].x * r[1] + acc[2].x * r[2] + acc[3].x * r[3]);
    o.y = 0.25f * (acc[0].y * r[0] + acc[1].y * r[1] + acc[2].y * r[2] + acc[3].y * r[3]);
    o.z = 0.25f * (acc[0].z * r[0] + acc[1].z * r[1] + acc[2].z * r[2] + acc[3].z * r[3]);
    o.w = 0.25f * (acc[0].w * r[0] + acc[1].w * r[1] + acc[2].w * r[2] + acc[3].w * r[3]);
    float4 bv = *(const float4*)(bias + l4);
    o.x = fmaxf(o.x + bv.x, 0.f);
    o.y = fmaxf(o.y + bv.y, 0.f);
    o.z = fmaxf(o.z + bv.z, 0.f);
    o.w = fmaxf(o.w + bv.w, 0.f);
    *(float4*)(out + (size_t)node * HIDC + l4) = o;
}

// ---------------- topk-pool scores: warp per node ----------------
__global__ __launch_bounds__(256)
void score_kernel(const float* __restrict__ h, const float* __restrict__ p,
                  float* __restrict__ score) {
    int wid = (blockIdx.x * blockDim.x + threadIdx.x) >> 5;
    int l = threadIdx.x & 31;
    if (wid >= NT) return;
    float4 pv = *(const float4*)(p + l * 4);
    float pn = pv.x * pv.x + pv.y * pv.y + pv.z * pv.z + pv.w * pv.w;
    float4 hv = *(const float4*)(h + (size_t)wid * HIDC + l * 4);
    float s = hv.x * pv.x + hv.y * pv.y + hv.z * pv.z + hv.w * pv.w;
#pragma unroll
    for (int off = 16; off; off >>= 1) {
        pn += __shfl_xor_sync(0xffffffffu, pn, off);
        s += __shfl_xor_sync(0xffffffffu, s, off);
    }
    if (l == 0) score[wid] = s / (sqrtf(pn) + 1e-16f);
}

// ---------------- per-graph top-k via bitonic sort of (score,index) keys ----------------
__global__ __launch_bounds__(512)
void topk_kernel(const float* __restrict__ score, const int* __restrict__ mask,
                 int Kkeep, int* __restrict__ keep) {
    __shared__ unsigned long long sk[NNODE];
    int g = blockIdx.x, t = threadIdx.x;
    for (int i = t; i < NNODE; i += 512) {
        int node = g * NNODE + i;
        float s = (mask && !mask[node]) ? -INFINITY : score[node];
        unsigned u = __float_as_uint(s);
        u = (u & 0x80000000u) ? ~u : (u | 0x80000000u);  // sortable
        sk[i] = ((unsigned long long)u << 32) | (unsigned)(0xFFFFFFFFu - (unsigned)i);
    }
    for (int size = 2; size <= NNODE; size <<= 1) {
        for (int stride = size >> 1; stride > 0; stride >>= 1) {
            __syncthreads();
            int lo = 2 * t - (t & (stride - 1));
            bool desc = ((lo & size) == 0);
            unsigned long long a = sk[lo], b = sk[lo + stride];
            bool sw = desc ? (a < b) : (a > b);
            if (sw) { sk[lo] = b; sk[lo + stride] = a; }
        }
    }
    __syncthreads();
    for (int r = t; r < NNODE; r += 512) {
        int li = (int)(0xFFFFFFFFu - (unsigned)(sk[r] & 0xFFFFFFFFull));
        keep[g * NNODE + li] = (r < Kkeep) ? 1 : 0;
    }
}

// ---------------- gate multiply: hp = h * tanh(score) ----------------
__global__ void gate_kernel(const float* __restrict__ h, const float* __restrict__ score,
                            float* __restrict__ out) {
    int i = blockIdx.x * blockDim.x + threadIdx.x;
    if (i < NT * HIDC) out[i] = h[i] * tanhf(score[i >> 7]);
}

// ---------------- global max / mean pool over keep2 (gated h2) ----------------
__global__ __launch_bounds__(128)
void pool_kernel(const float* __restrict__ h2, const float* __restrict__ score2) {
    __shared__ float sg[NNODE];
    __shared__ unsigned char skp[NNODE];
    int b = blockIdx.x, c = threadIdx.x;
    for (int i = c; i < NNODE; i += 128) {
        int node = b * NNODE + i;
        int k = g_keep2[node];
        skp[i] = (unsigned char)k;
        sg[i] = k ? tanhf(score2[node]) : 0.f;
    }
    __syncthreads();
    float mx = -INFINITY, sm = 0.f;
    for (int i = 0; i < NNODE; i++) {
        if (skp[i]) {
            float v = h2[(size_t)(b * NNODE + i) * HIDC + c] * sg[i];
            mx = fmaxf(mx, v);
            sm += v;
        }
    }
    g_gmx[b * HIDC + c] = mx;
    g_gav[b * HIDC + c] = sm / (float)KEEP2;
}

// ---------------- final MLP: [gmx, gav, action] -> 128 -> 128 -> 1 ----------------
__global__ __launch_bounds__(128)
void mlp_kernel(const float* __restrict__ action,
                const float* __restrict__ Wf1, const float* __restrict__ bf1,
                const float* __restrict__ Wf2, const float* __restrict__ bf2,
                const float* __restrict__ Wf3, const float* __restrict__ bf3,
                float* __restrict__ out) {
    __shared__ float sz[2 * HIDC + NR];
    __shared__ float s1[HIDC];
    __shared__ float sred[HIDC];
    int b = blockIdx.x, c = threadIdx.x;
    sz[c] = g_gmx[b * HIDC + c];
    sz[HIDC + c] = g_gav[b * HIDC + c];
    if (c < NR) sz[2 * HIDC + c] = action[b * NR + c];
    __syncthreads();
    float a = bf1[c];
    for (int k = 0; k < 2 * HIDC + NR; k++) a = fmaf(sz[k], Wf1[k * HIDC + c], a);
    s1[c] = fmaxf(a, 0.f);
    __syncthreads();
    float a2 = bf2[c];
    for (int k = 0; k < HIDC; k++) a2 = fmaf(s1[k], Wf2[k * HIDC + c], a2);
    sred[c] = fmaxf(a2, 0.f) * Wf3[c];
    __syncthreads();
    for (int off = 64; off; off >>= 1) {
        if (c < off) sred[c] += sred[c + off];
        __syncthreads();
    }
    if (c == 0) out[b] = sred[0] + bf3[0];
}

// ---------------- launch ----------------
extern "C" void kernel_launch(void* const* d_in, const int* in_sizes, int n_in,
                              void* d_out, int out_size) {
    const float* x       = (const float*)d_in[0];
    const float* ea      = (const float*)d_in[1];
    const float* action  = (const float*)d_in[2];
    const float* W1l     = (const float*)d_in[3];
    const float* b1l     = (const float*)d_in[4];
    const float* W1r     = (const float*)d_in[5];
    const float* b1r     = (const float*)d_in[6];
    const float* W1e     = (const float*)d_in[7];
    const float* att1    = (const float*)d_in[8];
    const float* bias1   = (const float*)d_in[9];
    const float* W2l     = (const float*)d_in[10];
    const float* b2l     = (const float*)d_in[11];
    const float* W2r     = (const float*)d_in[12];
    const float* b2r     = (const float*)d_in[13];
    const float* W2e     = (const float*)d_in[14];
    const float* att2    = (const float*)d_in[15];
    const float* bias2   = (const float*)d_in[16];
    const float* p1      = (const float*)d_in[17];
    const float* p2      = (const float*)d_in[18];
    const float* Wf1     = (const float*)d_in[19];
    const float* bf1     = (const float*)d_in[20];
    const float* Wf2     = (const float*)d_in[21];
    const float* bf2     = (const float*)d_in[22];
    const float* Wf3     = (const float*)d_in[23];
    const float* bf3     = (const float*)d_in[24];
    const int*   ei      = (const int*)d_in[25];
    const int* src = ei;
    const int* dst = ei + NE;
    float* out = (float*)d_out;

    // device-symbol pointers for kernels that take them as args
    float *xl, *xr, *h1, *hp1, *h2, *s1, *s2;
    int *k1p, *k2p;
    cudaGetSymbolAddress((void**)&xl,  g_xl);
    cudaGetSymbolAddress((void**)&xr,  g_xr);
    cudaGetSymbolAddress((void**)&h1,  g_h1);
    cudaGetSymbolAddress((void**)&hp1, g_hp1);
    cudaGetSymbolAddress((void**)&h2,  g_h2);
    cudaGetSymbolAddress((void**)&s1,  g_score1);
    cudaGetSymbolAddress((void**)&s2,  g_score2);
    cudaGetSymbolAddress((void**)&k1p, g_keep1);
    cudaGetSymbolAddress((void**)&k2p, g_keep2);

    // CSR by dst
    zero_kernel<<<NT / 256, 256>>>();
    count_kernel<<<NE / 256, 256>>>(dst);
    scan_kernel<<<1, 1024>>>();
    scatter_kernel<<<NE / 256, 256>>>(dst);

    dim3 ggrid(HDH / 64, NT / 64);
    // layer 1
    sgemm_bias<<<ggrid, 256>>>(x, W1l, b1l, xl, NT, F_IN, HDH);
    sgemm_bias<<<ggrid, 256>>>(x, W1r, b1r, xr, NT, F_IN, HDH);
    gat_kernel<<<NT / 8, 256>>>(xl, xr, ea, W1e, att1, bias1, src, nullptr, h1);
    // pool 1
    score_kernel<<<NT / 8, 256>>>(h1, p1, s1);
    topk_kernel<<<BATCH, 512>>>(s1, nullptr, KEEP1, k1p);
    gate_kernel<<<(NT * HIDC) / 256, 256>>>(h1, s1, hp1);
    // layer 2
    sgemm_bias<<<ggrid, 256>>>(hp1, W2l, b2l, xl, NT, HIDC, HDH);
    sgemm_bias<<<ggrid, 256>>>(hp1, W2r, b2r, xr, NT, HIDC, HDH);
    gat_kernel<<<NT / 8, 256>>>(xl, xr, ea, W2e, att2, bias2, src, k1p, h2);
    // pool 2
    score_kernel<<<NT / 8, 256>>>(h2, p2, s2);
    topk_kernel<<<BATCH, 512>>>(s2, k1p, KEEP2, k2p);
    // readout
    pool_kernel<<<BATCH, 128>>>(h2, s2);
    mlp_kernel<<<BATCH, 128>>>(action, Wf1, bf1, Wf2, bf2, Wf3, bf3, out);
}

// round 2
// speedup vs baseline: 1.1492x; 1.1492x over previous
#include <cuda_runtime.h>
#include <math.h>
#include <stdint.h>

// ---------------- problem constants ----------------
#define BATCH 32
#define NNODE 1024
#define NT    32768          // BATCH*NNODE
#define DEG   8
#define NE    262144         // NT*DEG
#define F_IN  64
#define HIDC  128
#define EDIM  16
#define NR    16
#define HD    4
#define HDH   512            // HD*HIDC
#define KEEP1 820
#define KEEP2 656
#define NEG_SLOPE 0.2f

typedef unsigned long long ull;

// ---------------- f32x2 packed helpers (sm_100a) ----------------
__device__ __forceinline__ float f2lo(ull u) { return __uint_as_float((unsigned)u); }
__device__ __forceinline__ float f2hi(ull u) { return __uint_as_float((unsigned)(u >> 32)); }
__device__ __forceinline__ ull fdup(float s) {
    ull r; unsigned u = __float_as_uint(s);
    asm("mov.b64 %0, {%1, %1};" : "=l"(r) : "r"(u));
    return r;
}
// d = a*b + d
#define FMA2(d, a, b) asm("fma.rn.f32x2 %0, %2, %3, %1;" : "=l"(d) : "l"(d), "l"(a), "l"(b))
// d = a*b + c
#define FMA2G(d, a, b, c) asm("fma.rn.f32x2 %0, %1, %2, %3;" : "=l"(d) : "l"(a), "l"(b), "l"(c))
__device__ __forceinline__ ull mul2(ull a, ull b) {
    ull r; asm("mul.rn.f32x2 %0, %1, %2;" : "=l"(r) : "l"(a), "l"(b)); return r;
}

// ---------------- device scratch ----------------
__device__ float g_xl[(size_t)NT * HDH];
__device__ float g_xr[(size_t)NT * HDH];
__device__ float g_h1[(size_t)NT * HIDC];
__device__ float g_hp1[(size_t)NT * HIDC];
__device__ float g_h2[(size_t)NT * HIDC];
__device__ float g_score1[NT];
__device__ float g_score2[NT];
__device__ int   g_keep1[NT];
__device__ int   g_keep2[NT];
__device__ int   g_cnt[NT];
__device__ int   g_pos[NT];
__device__ int   g_row[NT + 1];
__device__ int   g_csr[NE];
__device__ float g_gmx[BATCH * HIDC];
__device__ float g_gav[BATCH * HIDC];

// ---------------- CSR build ----------------
__global__ void zero_kernel() {
    int i = blockIdx.x * blockDim.x + threadIdx.x;
    if (i < NT) { g_cnt[i] = 0; g_pos[i] = 0; }
}
__global__ void count_kernel(const int* __restrict__ dst) {
    int e = blockIdx.x * blockDim.x + threadIdx.x;
    if (e < NE) atomicAdd(&g_cnt[dst[e]], 1);
}
__global__ void scan_kernel() {
    __shared__ int s[1024];
    int t = threadIdx.x;
    int base = t * 32;
    int vals[32];
    int loc = 0;
#pragma unroll
    for (int j = 0; j < 32; j++) { vals[j] = g_cnt[base + j]; loc += vals[j]; }
    s[t] = loc;
    __syncthreads();
    for (int off = 1; off < 1024; off <<= 1) {
        int v = 0;
        if (t >= off) v = s[t - off];
        __syncthreads();
        s[t] += v;
        __syncthreads();
    }
    int run = s[t] - loc;
#pragma unroll
    for (int j = 0; j < 32; j++) { g_row[base + j] = run; run += vals[j]; }
    if (t == 1023) g_row[NT] = run;
}
__global__ void scatter_kernel(const int* __restrict__ dst) {
    int e = blockIdx.x * blockDim.x + threadIdx.x;
    if (e < NE) {
        int d = dst[e];
        int p = atomicAdd(&g_pos[d], 1);
        g_csr[g_row[d] + p] = e;
    }
}

// ---------------- SGEMM v2: f32x2, BM=128 BN=128 BK=16, 8x8/thread ----------------
// Computes BOTH C0 = A@W0+b0 and C1 = A@W1+b1 (grid.x = 8: first 4 col-blocks -> W0).
__global__ __launch_bounds__(256)
void sgemm2(const float* __restrict__ A,
            const float* __restrict__ W0, const float* __restrict__ W1,
            const float* __restrict__ bias0, const float* __restrict__ bias1,
            float* __restrict__ C0, float* __restrict__ C1, int K) {
    __shared__ float sA[16][128];
    __shared__ float sB[16][128];
    int tid = threadIdx.x;
    int which = blockIdx.x >> 2;
    const float* W = which ? W1 : W0;
    const float* bias = which ? bias1 : bias0;
    float* C = which ? C1 : C0;
    int col0 = (blockIdx.x & 3) * 128;
    int row0 = blockIdx.y * 128;

    int tr = tid >> 4, tc = tid & 15;

    // global load indices (2 float4 each for A and B per tile)
    int aidx0 = tid * 2, aidx1 = tid * 2 + 1;
    int ar0 = aidx0 >> 2, ak0 = (aidx0 & 3) * 4;
    int ar1 = aidx1 >> 2, ak1 = (aidx1 & 3) * 4;
    int bk0 = aidx0 >> 5, bc0 = (aidx0 & 31) * 4;
    int bk1 = aidx1 >> 5, bc1 = (aidx1 & 31) * 4;
    const float* Abase = A + (size_t)(row0)*K;
    const float* Wbase = W + col0;

    ull acc[4][8];
#pragma unroll
    for (int p = 0; p < 4; p++)
#pragma unroll
        for (int j = 0; j < 8; j++) acc[p][j] = 0ull;

    // load first tile
    {
        float4 a0 = *(const float4*)(Abase + (size_t)ar0 * K + ak0);
        float4 a1 = *(const float4*)(Abase + (size_t)ar1 * K + ak1);
        float4 b0 = *(const float4*)(Wbase + (size_t)bk0 * 512 + bc0);
        float4 b1 = *(const float4*)(Wbase + (size_t)bk1 * 512 + bc1);
        sA[ak0 + 0][ar0] = a0.x; sA[ak0 + 1][ar0] = a0.y; sA[ak0 + 2][ar0] = a0.z; sA[ak0 + 3][ar0] = a0.w;
        sA[ak1 + 0][ar1] = a1.x; sA[ak1 + 1][ar1] = a1.y; sA[ak1 + 2][ar1] = a1.z; sA[ak1 + 3][ar1] = a1.w;
        *(float4*)&sB[bk0][bc0] = b0;
        *(float4*)&sB[bk1][bc1] = b1;
    }
    __syncthreads();

    for (int k0 = 0; k0 < K; k0 += 16) {
        bool has_next = (k0 + 16) < K;
        float4 pa0, pa1, pb0, pb1;
        if (has_next) {
            int kn = k0 + 16;
            pa0 = *(const float4*)(Abase + (size_t)ar0 * K + kn + ak0);
            pa1 = *(const float4*)(Abase + (size_t)ar1 * K + kn + ak1);
            pb0 = *(const float4*)(Wbase + (size_t)(kn + bk0) * 512 + bc0);
            pb1 = *(const float4*)(Wbase + (size_t)(kn + bk1) * 512 + bc1);
        }
#pragma unroll
        for (int kk = 0; kk < 16; kk++) {
            ulonglong2 av0 = *(const ulonglong2*)&sA[kk][tr * 8];
            ulonglong2 av1 = *(const ulonglong2*)&sA[kk][tr * 8 + 4];
            float4 b0 = *(const float4*)&sB[kk][tc * 8];
            float4 b1 = *(const float4*)&sB[kk][tc * 8 + 4];
            ull a2[4] = {av0.x, av0.y, av1.x, av1.y};
            ull bd[8] = {fdup(b0.x), fdup(b0.y), fdup(b0.z), fdup(b0.w),
                         fdup(b1.x), fdup(b1.y), fdup(b1.z), fdup(b1.w)};
#pragma unroll
            for (int p = 0; p < 4; p++)
#pragma unroll
                for (int j = 0; j < 8; j++) FMA2(acc[p][j], a2[p], bd[j]);
        }
        __syncthreads();
        if (has_next) {
            sA[ak0 + 0][ar0] = pa0.x; sA[ak0 + 1][ar0] = pa0.y; sA[ak0 + 2][ar0] = pa0.z; sA[ak0 + 3][ar0] = pa0.w;
            sA[ak1 + 0][ar1] = pa1.x; sA[ak1 + 1][ar1] = pa1.y; sA[ak1 + 2][ar1] = pa1.z; sA[ak1 + 3][ar1] = pa1.w;
            *(float4*)&sB[bk0][bc0] = pb0;
            *(float4*)&sB[bk1][bc1] = pb1;
            __syncthreads();
        }
    }

    float4 bv0 = *(const float4*)(bias + col0 + tc * 8);
    float4 bv1 = *(const float4*)(bias + col0 + tc * 8 + 4);
    float bb[8] = {bv0.x, bv0.y, bv0.z, bv0.w, bv1.x, bv1.y, bv1.z, bv1.w};
#pragma unroll
    for (int i = 0; i < 8; i++) {
        int p = i >> 1, hf = i & 1;
        float v[8];
#pragma unroll
        for (int j = 0; j < 8; j++) v[j] = (hf ? f2hi(acc[p][j]) : f2lo(acc[p][j])) + bb[j];
        float* dst = C + (size_t)(row0 + tr * 8 + i) * 512 + col0 + tc * 8;
        *(float4*)dst = make_float4(v[0], v[1], v[2], v[3]);
        *(float4*)(dst + 4) = make_float4(v[4], v[5], v[6], v[7]);
    }
}

// ---------------- GATv2 v2: warp/node, 4-edge chunks, f32x2 ----------------
#define EAC(e, k) (((k) & 3) == 0 ? eav[e][(k) >> 2].x : ((k) & 3) == 1 ? eav[e][(k) >> 2].y \
                   : ((k) & 3) == 2 ? eav[e][(k) >> 2].z : eav[e][(k) >> 2].w)

__global__ __launch_bounds__(128)
void gat_kernel(const float* __restrict__ xl, const float* __restrict__ xr,
                const float* __restrict__ ea_g, const float* __restrict__ We,
                const float* __restrict__ att, const float* __restrict__ bias,
                const int* __restrict__ src, const int* __restrict__ kp,
                float* __restrict__ out) {
    __shared__ float sWe[16][512];
    __shared__ float sAtt[512];
    for (int i = threadIdx.x; i < 2048; i += 128)
        ((float4*)&sWe[0][0])[i] = ((const float4*)We)[i];
    if (threadIdx.x < 128) ((float4*)sAtt)[threadIdx.x] = ((const float4*)att)[threadIdx.x];
    __syncthreads();

    int warp = threadIdx.x >> 5, lane = threadIdx.x & 31;
    int node = blockIdx.x * 4 + warp;
    int l4 = lane * 4;

    float4 xrv[HD], attv[HD];
    ull acc2[HD][2];
    float mh[HD], dh[HD];
#pragma unroll
    for (int h = 0; h < HD; h++) {
        xrv[h] = *(const float4*)(xr + (size_t)node * HDH + h * HIDC + l4);
        attv[h] = *(const float4*)(&sAtt[h * HIDC + l4]);
        acc2[h][0] = 0ull; acc2[h][1] = 0ull;
        mh[h] = -INFINITY; dh[h] = 0.f;
    }

    bool okd = (kp == nullptr) || (kp[node] != 0);
    int beg = g_row[node];
    int end = okd ? g_row[node + 1] : beg;

    for (int base = beg; base < end; base += 4) {
        int nv = end - base;
        int sid[4]; bool val[4];
        float4 eav[4][4];
#pragma unroll
        for (int e = 0; e < 4; e++) {
            bool v = e < nv;
            int ee = g_csr[v ? base + e : base];
            int ss = src[ee];
            if (kp && !kp[ss]) v = false;
            sid[e] = ss; val[e] = v;
            const float4* p = (const float4*)(ea_g + (size_t)ee * EDIM);
            eav[e][0] = p[0]; eav[e][1] = p[1]; eav[e][2] = p[2]; eav[e][3] = p[3];
        }
#pragma unroll
        for (int h = 0; h < HD; h++) {
            ull ef[4][2];
#pragma unroll
            for (int e = 0; e < 4; e++) { ef[e][0] = 0ull; ef[e][1] = 0ull; }
#pragma unroll
            for (int k = 0; k < 16; k++) {
                ulonglong2 w2 = *(const ulonglong2*)&sWe[k][h * HIDC + l4];
#pragma unroll
                for (int e = 0; e < 4; e++) {
                    ull sd = fdup(EAC(e, k));
                    FMA2(ef[e][0], sd, w2.x);
                    FMA2(ef[e][1], sd, w2.y);
                }
            }
            ulonglong2 xlv[4];
            float part[4];
#pragma unroll
            for (int e = 0; e < 4; e++) {
                ulonglong2 xv = *(const ulonglong2*)(xl + (size_t)sid[e] * HDH + h * HIDC + l4);
                xlv[e] = xv;
                float tx = f2lo(xv.x) + xrv[h].x + f2lo(ef[e][0]);
                float ty = f2hi(xv.x) + xrv[h].y + f2hi(ef[e][0]);
                float tz = f2lo(xv.y) + xrv[h].z + f2lo(ef[e][1]);
                float tw = f2hi(xv.y) + xrv[h].w + f2hi(ef[e][1]);
                tx = tx > 0.f ? tx : NEG_SLOPE * tx;
                ty = ty > 0.f ? ty : NEG_SLOPE * ty;
                tz = tz > 0.f ? tz : NEG_SLOPE * tz;
                tw = tw > 0.f ? tw : NEG_SLOPE * tw;
                part[e] = tx * attv[h].x + ty * attv[h].y + tz * attv[h].z + tw * attv[h].w;
            }
#pragma unroll
            for (int off = 16; off; off >>= 1)
#pragma unroll
                for (int e = 0; e < 4; e++)
                    part[e] += __shfl_xor_sync(0xffffffffu, part[e], off);
#pragma unroll
            for (int e = 0; e < 4; e++) {
                if (val[e]) {
                    float L = part[e];
                    float nm = fmaxf(mh[h], L);
                    float sc = __expf(mh[h] - nm);   // 0 when mh==-inf
                    float w = __expf(L - nm);
                    dh[h] = dh[h] * sc + w;
                    ull scd = fdup(sc), wd = fdup(w);
                    ull t0 = mul2(xlv[e].x, wd);
                    ull t1 = mul2(xlv[e].y, wd);
                    FMA2G(acc2[h][0], acc2[h][0], scd, t0);
                    FMA2G(acc2[h][1], acc2[h][1], scd, t1);
                    mh[h] = nm;
                }
            }
        }
    }

    float r[HD];
#pragma unroll
    for (int h = 0; h < HD; h++) r[h] = 1.f / (dh[h] + 1e-16f);
    float ox = 0.f, oy = 0.f, oz = 0.f, ow = 0.f;
#pragma unroll
    for (int h = 0; h < HD; h++) {
        ox += f2lo(acc2[h][0]) * r[h];
        oy += f2hi(acc2[h][0]) * r[h];
        oz += f2lo(acc2[h][1]) * r[h];
        ow += f2hi(acc2[h][1]) * r[h];
    }
    float4 bv = *(const float4*)(bias + l4);
    float4 o;
    o.x = fmaxf(0.25f * ox + bv.x, 0.f);
    o.y = fmaxf(0.25f * oy + bv.y, 0.f);
    o.z = fmaxf(0.25f * oz + bv.z, 0.f);
    o.w = fmaxf(0.25f * ow + bv.w, 0.f);
    *(float4*)(out + (size_t)node * HIDC + l4) = o;
}

// ---------------- topk-pool scores ----------------
__global__ __launch_bounds__(256)
void score_kernel(const float* __restrict__ h, const float* __restrict__ p,
                  float* __restrict__ score) {
    int wid = (blockIdx.x * blockDim.x + threadIdx.x) >> 5;
    int l = threadIdx.x & 31;
    if (wid >= NT) return;
    float4 pv = *(const float4*)(p + l * 4);
    float pn = pv.x * pv.x + pv.y * pv.y + pv.z * pv.z + pv.w * pv.w;
    float4 hv = *(const float4*)(h + (size_t)wid * HIDC + l * 4);
    float s = hv.x * pv.x + hv.y * pv.y + hv.z * pv.z + hv.w * pv.w;
#pragma unroll
    for (int off = 16; off; off >>= 1) {
        pn += __shfl_xor_sync(0xffffffffu, pn, off);
        s += __shfl_xor_sync(0xffffffffu, s, off);
    }
    if (l == 0) score[wid] = s / (sqrtf(pn) + 1e-16f);
}

// ---------------- per-graph top-k via bitonic sort ----------------
__global__ __launch_bounds__(512)
void topk_kernel(const float* __restrict__ score, const int* __restrict__ mask,
                 int Kkeep, int* __restrict__ keep) {
    __shared__ unsigned long long sk[NNODE];
    int g = blockIdx.x, t = threadIdx.x;
    for (int i = t; i < NNODE; i += 512) {
        int node = g * NNODE + i;
        float s = (mask && !mask[node]) ? -INFINITY : score[node];
        unsigned u = __float_as_uint(s);
        u = (u & 0x80000000u) ? ~u : (u | 0x80000000u);
        sk[i] = ((unsigned long long)u << 32) | (unsigned)(0xFFFFFFFFu - (unsigned)i);
    }
    for (int size = 2; size <= NNODE; size <<= 1) {
        for (int stride = size >> 1; stride > 0; stride >>= 1) {
            __syncthreads();
            int lo = 2 * t - (t & (stride - 1));
            bool desc = ((lo & size) == 0);
            unsigned long long a = sk[lo], b = sk[lo + stride];
            bool sw = desc ? (a < b) : (a > b);
            if (sw) { sk[lo] = b; sk[lo + stride] = a; }
        }
    }
    __syncthreads();
    for (int r = t; r < NNODE; r += 512) {
        int li = (int)(0xFFFFFFFFu - (unsigned)(sk[r] & 0xFFFFFFFFull));
        keep[g * NNODE + li] = (r < Kkeep) ? 1 : 0;
    }
}

// ---------------- gate multiply ----------------
__global__ void gate_kernel(const float* __restrict__ h, const float* __restrict__ score,
                            float* __restrict__ out) {
    int i = blockIdx.x * blockDim.x + threadIdx.x;
    if (i < NT * HIDC) out[i] = h[i] * tanhf(score[i >> 7]);
}

// ---------------- global max / mean pool ----------------
__global__ __launch_bounds__(1024)
void pool_kernel(const float* __restrict__ h2, const float* __restrict__ score2) {
    __shared__ float sg[NNODE];
    __shared__ unsigned char skp[NNODE];
    __shared__ float rmx[8][HIDC];
    __shared__ float rsm[8][HIDC];
    int b = blockIdx.x, t = threadIdx.x;
    {
        int node = b * NNODE + t;
        int k = g_keep2[node];
        skp[t] = (unsigned char)k;
        sg[t] = k ? tanhf(score2[node]) : 0.f;
    }
    __syncthreads();
    int c = t & 127, sl = t >> 7;
    float mx = -INFINITY, sm = 0.f;
    for (int i = sl; i < NNODE; i += 8) {
        if (skp[i]) {
            float v = h2[(size_t)(b * NNODE + i) * HIDC + c] * sg[i];
            mx = fmaxf(mx, v);
            sm += v;
        }
    }
    rmx[sl][c] = mx; rsm[sl][c] = sm;
    __syncthreads();
    if (t < HIDC) {
        float m = rmx[0][t], s = rsm[0][t];
#pragma unroll
        for (int j = 1; j < 8; j++) { m = fmaxf(m, rmx[j][t]); s += rsm[j][t]; }
        g_gmx[b * HIDC + t] = m;
        g_gav[b * HIDC + t] = s / (float)KEEP2;
    }
}

// ---------------- final MLP ----------------
__global__ __launch_bounds__(128)
void mlp_kernel(const float* __restrict__ action,
                const float* __restrict__ Wf1, const float* __restrict__ bf1,
                const float* __restrict__ Wf2, const float* __restrict__ bf2,
                const float* __restrict__ Wf3, const float* __restrict__ bf3,
                float* __restrict__ out) {
    __shared__ float sz[2 * HIDC + NR];
    __shared__ float s1[HIDC];
    __shared__ float sred[HIDC];
    int b = blockIdx.x, c = threadIdx.x;
    sz[c] = g_gmx[b * HIDC + c];
    sz[HIDC + c] = g_gav[b * HIDC + c];
    if (c < NR) sz[2 * HIDC + c] = action[b * NR + c];
    __syncthreads();
    float a = bf1[c];
    for (int k = 0; k < 2 * HIDC + NR; k++) a = fmaf(sz[k], Wf1[k * HIDC + c], a);
    s1[c] = fmaxf(a, 0.f);
    __syncthreads();
    float a2 = bf2[c];
    for (int k = 0; k < HIDC; k++) a2 = fmaf(s1[k], Wf2[k * HIDC + c], a2);
    sred[c] = fmaxf(a2, 0.f) * Wf3[c];
    __syncthreads();
    for (int off = 64; off; off >>= 1) {
        if (c < off) sred[c] += sred[c + off];
        __syncthreads();
    }
    if (c == 0) out[b] = sred[0] + bf3[0];
}

// ---------------- launch ----------------
extern "C" void kernel_launch(void* const* d_in, const int* in_sizes, int n_in,
                              void* d_out, int out_size) {
    const float* x      = (const float*)d_in[0];
    const float* ea     = (const float*)d_in[1];
    const float* action = (const float*)d_in[2];
    const float* W1l    = (const float*)d_in[3];
    const float* b1l    = (const float*)d_in[4];
    const float* W1r    = (const float*)d_in[5];
    const float* b1r    = (const float*)d_in[6];
    const float* W1e    = (const float*)d_in[7];
    const float* att1   = (const float*)d_in[8];
    const float* bias1  = (const float*)d_in[9];
    const float* W2l    = (const float*)d_in[10];
    const float* b2l    = (const float*)d_in[11];
    const float* W2r    = (const float*)d_in[12];
    const float* b2r    = (const float*)d_in[13];
    const float* W2e    = (const float*)d_in[14];
    const float* att2   = (const float*)d_in[15];
    const float* bias2  = (const float*)d_in[16];
    const float* p1     = (const float*)d_in[17];
    const float* p2     = (const float*)d_in[18];
    const float* Wf1    = (const float*)d_in[19];
    const float* bf1    = (const float*)d_in[20];
    const float* Wf2    = (const float*)d_in[21];
    const float* bf2    = (const float*)d_in[22];
    const float* Wf3    = (const float*)d_in[23];
    const float* bf3    = (const float*)d_in[24];
    const int*   ei     = (const int*)d_in[25];
    const int* src = ei;
    const int* dst = ei + NE;
    float* out = (float*)d_out;

    float *xl, *xr, *h1, *hp1, *h2, *s1, *s2;
    int *k1p, *k2p;
    cudaGetSymbolAddress((void**)&xl,  g_xl);
    cudaGetSymbolAddress((void**)&xr,  g_xr);
    cudaGetSymbolAddress((void**)&h1,  g_h1);
    cudaGetSymbolAddress((void**)&hp1, g_hp1);
    cudaGetSymbolAddress((void**)&h2,  g_h2);
    cudaGetSymbolAddress((void**)&s1,  g_score1);
    cudaGetSymbolAddress((void**)&s2,  g_score2);
    cudaGetSymbolAddress((void**)&k1p, g_keep1);
    cudaGetSymbolAddress((void**)&k2p, g_keep2);

    // CSR by dst
    zero_kernel<<<NT / 256, 256>>>();
    count_kernel<<<NE / 256, 256>>>(dst);
    scan_kernel<<<1, 1024>>>();
    scatter_kernel<<<NE / 256, 256>>>(dst);

    dim3 ggrid(8, NT / 128);
    // layer 1
    sgemm2<<<ggrid, 256>>>(x, W1l, W1r, b1l, b1r, xl, xr, F_IN);
    gat_kernel<<<NT / 4, 128>>>(xl, xr, ea, W1e, att1, bias1, src, nullptr, h1);
    // pool 1
    score_kernel<<<NT / 8, 256>>>(h1, p1, s1);
    topk_kernel<<<BATCH, 512>>>(s1, nullptr, KEEP1, k1p);
    gate_kernel<<<(NT * HIDC) / 256, 256>>>(h1, s1, hp1);
    // layer 2
    sgemm2<<<ggrid, 256>>>(hp1, W2l, W2r, b2l, b2r, xl, xr, HIDC);
    gat_kernel<<<NT / 4, 128>>>(xl, xr, ea, W2e, att2, bias2, src, k1p, h2);
    // pool 2
    score_kernel<<<NT / 8, 256>>>(h2, p2, s2);
    topk_kernel<<<BATCH, 512>>>(s2, k1p, KEEP2, k2p);
    // readout
    pool_kernel<<<BATCH, 1024>>>(h2, s2);
    mlp_kernel<<<BATCH, 128>>>(action, Wf1, bf1, Wf2, bf2, Wf3, bf3, out);
}